// round 2
// baseline (speedup 1.0000x reference)
#include <cuda_runtime.h>
#include <cstdint>

#define NB 1024   // batch
#define NT 64     // time steps
#define ND 512    // input dim
#define NH 512    // hidden dim
#define NG 2048   // 4*H (gates)
#define NK 1024   // D + H fused K

// ---------------- static device scratch (no allocations allowed) ----------
__device__ float g_WRt[NG * NK];     // fused [W;R]^T, gate-interleaved, tf32-rounded (8MB)
__device__ float g_biasp[NG];        // permuted bias
__device__ float g_hbuf[2][NB * NH]; // double-buffered hidden state
__device__ float g_cbuf[NB * NH];    // cell state

__device__ __forceinline__ uint32_t f2tf32(float f) {
    uint32_t r;
    asm("cvt.rna.tf32.f32 %0, %1;" : "=r"(r) : "f"(f));
    return r;
}

// Build WRt[n][k]: n = h_idx*4 + gate (interleaved so a 128-col tile holds all
// 4 gates of 32 hidden units); k<512 from kernel W[k][j], else recurrent R.
// Original gate-major column j = gate*512 + h_idx.
__global__ void prep_kernel(const float* __restrict__ W,
                            const float* __restrict__ R,
                            const float* __restrict__ bias) {
    int tid = blockIdx.x * blockDim.x + threadIdx.x;
    int nthr = gridDim.x * blockDim.x;
    for (int i = tid; i < NG * NK; i += nthr) {
        int n = i >> 10;            // / NK
        int k = i & (NK - 1);
        int j = (n & 3) * NH + (n >> 2);
        float v = (k < ND) ? W[k * NG + j] : R[(k - ND) * NG + j];
        g_WRt[i] = __uint_as_float(f2tf32(v));
    }
    if (tid < NG) g_biasp[tid] = bias[(tid & 3) * NH + (tid >> 2)];
    for (int i = tid; i < NB * NH; i += nthr) {
        g_hbuf[1][i] = 0.f;   // step 0 reads buffer 1
        g_cbuf[i] = 0.f;
    }
}

// ---------------- tf32 m16n8k8 mma ----------------------------------------
__device__ __forceinline__ void mma_tf32(float* c, const uint32_t* a, const uint32_t* b) {
    asm volatile(
        "mma.sync.aligned.m16n8k8.row.col.f32.tf32.tf32.f32 "
        "{%0,%1,%2,%3}, {%4,%5,%6,%7}, {%8,%9}, {%0,%1,%2,%3};\n"
        : "+f"(c[0]), "+f"(c[1]), "+f"(c[2]), "+f"(c[3])
        : "r"(a[0]), "r"(a[1]), "r"(a[2]), "r"(a[3]),
          "r"(b[0]), "r"(b[1]));
}

__device__ __forceinline__ float sigmoidf_(float x) {
    return __fdividef(1.f, 1.f + __expf(-x));
}
__device__ __forceinline__ float tanhf_(float x) {
    return 2.f * sigmoidf_(2.f * x) - 1.f;
}

#define KC   16   // K chunk per smem stage
#define SPAD 20   // smem row pitch (conflict-free for fragment pattern)

// One LSTM step: z = [x_t | h_{t-1}] @ WRt^T + bias, fused gate epilogue.
// CTA tile 128(M: batch) x 128(N: 32 hidden units x 4 gates). grid (16, 8).
__global__ __launch_bounds__(256) void lstm_step(
    const float* __restrict__ x, float* __restrict__ out, int t)
{
    __shared__ uint32_t As[128 * SPAD];
    __shared__ uint32_t Bs[128 * SPAD];

    const float* __restrict__ hsrc = g_hbuf[(t + 1) & 1];
    float* __restrict__ hdst = g_hbuf[t & 1];

    const int tid = threadIdx.x;
    const int bm = blockIdx.y * 128;   // batch base
    const int bn = blockIdx.x * 128;   // interleaved-gate col base

    const int warp = tid >> 5, lane = tid & 31;
    const int wm = (warp >> 2) * 64;   // 2 warps over M
    const int wn = (warp & 3) * 32;    // 4 warps over N
    const int gid = lane >> 2, tg = lane & 3;

    float acc[4][4][4];
    #pragma unroll
    for (int i = 0; i < 4; i++)
        #pragma unroll
        for (int j = 0; j < 4; j++)
            #pragma unroll
            for (int r = 0; r < 4; r++) acc[i][j][r] = 0.f;

    for (int kt = 0; kt < NK / KC; kt++) {
        const int kk = kt * KC;
        // ---- load A (x_t or h) and B (WRt) tiles, cvt A to tf32 ----
        #pragma unroll
        for (int i = 0; i < 2; i++) {
            int idx = tid + i * 256;       // 0..511 -> 128 rows x 4 float4
            int m = idx >> 2;
            int kq = (idx & 3) << 2;
            int kg = kk + kq;
            float4 va;
            if (kg < ND)
                va = *(const float4*)(x + (size_t)(bm + m) * (NT * ND) + (size_t)t * ND + kg);
            else
                va = *(const float4*)(hsrc + (bm + m) * NH + (kg - ND));
            uint32_t* da = &As[m * SPAD + kq];
            da[0] = f2tf32(va.x); da[1] = f2tf32(va.y);
            da[2] = f2tf32(va.z); da[3] = f2tf32(va.w);
            float4 vb = *(const float4*)(g_WRt + (size_t)(bn + m) * NK + kg);
            uint32_t* db = &Bs[m * SPAD + kq];
            db[0] = __float_as_uint(vb.x); db[1] = __float_as_uint(vb.y);
            db[2] = __float_as_uint(vb.z); db[3] = __float_as_uint(vb.w);
        }
        __syncthreads();
        // ---- 2 x k8 MMA steps ----
        #pragma unroll
        for (int k8 = 0; k8 < KC; k8 += 8) {
            uint32_t a[4][4], b[4][2];
            #pragma unroll
            for (int mf = 0; mf < 4; mf++) {
                int rb = wm + mf * 16;
                a[mf][0] = As[(rb + gid) * SPAD + k8 + tg];
                a[mf][1] = As[(rb + gid + 8) * SPAD + k8 + tg];
                a[mf][2] = As[(rb + gid) * SPAD + k8 + tg + 4];
                a[mf][3] = As[(rb + gid + 8) * SPAD + k8 + tg + 4];
            }
            #pragma unroll
            for (int nf = 0; nf < 4; nf++) {
                int cb = wn + nf * 8;
                b[nf][0] = Bs[(cb + gid) * SPAD + k8 + tg];
                b[nf][1] = Bs[(cb + gid) * SPAD + k8 + tg + 4];
            }
            #pragma unroll
            for (int mf = 0; mf < 4; mf++)
                #pragma unroll
                for (int nf = 0; nf < 4; nf++)
                    mma_tf32(acc[mf][nf], a[mf], b[nf]);
        }
        __syncthreads();
    }

    // ---- fused LSTM epilogue ----
    // Accum cols (permuted): n = nblk + 2*tg (+1). Even tg holds gates (i,f),
    // odd tg holds (g,o) of the SAME hidden unit; exchange via shfl_xor(1).
    const bool evn = (lane & 1) == 0;
    #pragma unroll
    for (int nf = 0; nf < 4; nf++) {
        int nblk = bn + wn + nf * 8;
        float b0 = g_biasp[nblk + 2 * tg];
        float b1 = g_biasp[nblk + 2 * tg + 1];
        int hidx = (nblk >> 2) + (tg >> 1);
        #pragma unroll
        for (int mf = 0; mf < 4; mf++) {
            #pragma unroll
            for (int hh = 0; hh < 2; hh++) {
                float v0 = acc[mf][nf][hh * 2 + 0] + b0;
                float v1 = acc[mf][nf][hh * 2 + 1] + b1;
                float p0 = __shfl_xor_sync(0xffffffffu, v0, 1);
                float p1 = __shfl_xor_sync(0xffffffffu, v1, 1);
                if (evn) {
                    float iv = sigmoidf_(v0);
                    float fv = sigmoidf_(v1);
                    float gv = tanhf_(p0);
                    float ov = sigmoidf_(p1);
                    int brow = bm + wm + mf * 16 + gid + hh * 8;
                    int ci = brow * NH + hidx;
                    float cn = fv * g_cbuf[ci] + iv * gv;
                    float hn = ov * tanhf_(cn);
                    g_cbuf[ci] = cn;
                    hdst[ci] = hn;
                    out[(size_t)brow * (NT * NH) + (size_t)t * NH + hidx] = hn;
                }
            }
        }
    }
}

extern "C" void kernel_launch(void* const* d_in, const int* in_sizes, int n_in,
                              void* d_out, int out_size) {
    const float* x    = (const float*)d_in[0]; // input_context [1024,64,512]
    const float* W    = (const float*)d_in[1]; // kernel [512,2048]
    const float* R    = (const float*)d_in[2]; // recurrent_kernel [512,2048]
    const float* bias = (const float*)d_in[3]; // bias [2048]
    float* out = (float*)d_out;                // [1024,64,512]

    prep_kernel<<<512, 256>>>(W, R, bias);
    dim3 grid(16, 8);  // (N tiles, M tiles)
    for (int t = 0; t < NT; t++)
        lstm_step<<<grid, 256>>>(x, out, t);
}